// round 1
// baseline (speedup 1.0000x reference)
#include <cuda_runtime.h>
#include <math_constants.h>

#define BT 16
#define VH 6890
#define VO 2048
#define NH (BT*VH)          /* 110240 */
#define NO (BT*VO)          /* 32768  */
#define TPB 256
#define RPT 4
#define ROWCHUNK (TPB*RPT)  /* 1024 */
#define RCHUNKS ((VH+ROWCHUNK-1)/ROWCHUNK)  /* 7 */
#define JT 256
#define JCHUNKS (VO/JT)     /* 8 */

// Scratch (static __device__ — no allocations allowed)
__device__ float4   g_objP[2*NO];   // per object point: (-2x,-2y,-2z, x^2+y^2+z^2)
__device__ unsigned g_dh[2*NH];     // min d^2 bits, human rows  [ds][b][i]
__device__ unsigned g_do[2*NO];     // min d^2 bits, object cols [ds][b][j]
__device__ double   g_acc[8];       // [dir(h/o)][P, Spos, Sneg, Shub]

__global__ void k_init() {
    int i = blockIdx.x * blockDim.x + threadIdx.x;
    if (i < 2*NH) g_dh[i] = 0x7F800000u;  // +inf
    if (i < 2*NO) g_do[i] = 0x7F800000u;
    if (i < 8)    g_acc[i] = 0.0;
}

__global__ void k_prep(const float* __restrict__ o, const float* __restrict__ go) {
    int i = blockIdx.x * blockDim.x + threadIdx.x;
    if (i >= 2*NO) return;
    int ds = i >> 15;            // NO == 1<<15
    int r  = i & (NO - 1);
    const float* p = (ds ? go : o) + r * 3;
    float x = p[0], y = p[1], z = p[2];
    g_objP[i] = make_float4(-2.f*x, -2.f*y, -2.f*z,
                            fmaf(x, x, fmaf(y, y, z*z)));
}

__global__ void __launch_bounds__(TPB) k_pair(const float* __restrict__ h,
                                              const float* __restrict__ gh) {
    __shared__ float4   sB[JT];
    __shared__ unsigned sCol[JT];
    const int ds = blockIdx.z, b = blockIdx.y;
    const int rc = blockIdx.x / JCHUNKS, jc = blockIdx.x % JCHUNKS;
    const int t  = threadIdx.x;
    const int objOff = ds*NO + b*VO + jc*JT;

    sB[t]   = g_objP[objOff + t];   // TPB == JT
    sCol[t] = 0x7F800000u;

    const float* H = (ds ? gh : h) + (size_t)b * VH * 3;
    float hx[RPT], hy[RPT], hz[RPT], hh[RPT], rmin[RPT];
    const int row0 = rc * ROWCHUNK + t;
#pragma unroll
    for (int k = 0; k < RPT; k++) {
        int row = row0 + k * TPB;
        if (row < VH) {
            hx[k] = H[row*3+0]; hy[k] = H[row*3+1]; hz[k] = H[row*3+2];
            hh[k] = fmaf(hx[k], hx[k], fmaf(hy[k], hy[k], hz[k]*hz[k]));
        } else {
            hx[k] = hy[k] = hz[k] = 0.f;
            hh[k] = CUDART_INF_F;   // invalid row never wins col-min
        }
        rmin[k] = CUDART_INF_F;
    }
    __syncthreads();

#pragma unroll 4
    for (int j = 0; j < JT; j++) {
        float4 o = sB[j];           // broadcast LDS.128 (conflict-free)
        float cmin = CUDART_INF_F;
#pragma unroll
        for (int k = 0; k < RPT; k++) {
            float q = fmaf(hz[k], o.z, o.w);   // oo - 2 h·o
            q = fmaf(hy[k], o.y, q);
            q = fmaf(hx[k], o.x, q);
            rmin[k] = fminf(rmin[k], q);       // hh added after loop
            cmin    = fminf(cmin, q + hh[k]);  // full d^2 for col-min
        }
        unsigned u = __float_as_uint(fmaxf(cmin, 0.f));   // >=0 -> uint order == float order
        u = __reduce_min_sync(0xFFFFFFFFu, u);
        if ((t & 31) == 0) atomicMin(&sCol[j], u);
    }
    __syncthreads();

    atomicMin(&g_do[objOff + t], sCol[t]);
#pragma unroll
    for (int k = 0; k < RPT; k++) {
        int row = row0 + k * TPB;
        if (row < VH) {
            float d2 = fmaxf(rmin[k] + hh[k], 0.f);
            atomicMin(&g_dh[ds*NH + b*VH + row], __float_as_uint(d2));
        }
    }
}

__global__ void k_loss() {
    const int dir = blockIdx.y;          // 0 = human rows, 1 = object cols
    const int N   = dir ? NO : NH;
    int i = blockIdx.x * blockDim.x + threadIdx.x;
    float P = 0.f, Spos = 0.f, Sneg = 0.f, Shub = 0.f;
    if (i < N) {
        unsigned pb = dir ? g_do[i]      : g_dh[i];
        unsigned gb = dir ? g_do[NO + i] : g_dh[NH + i];
        float pd = sqrtf(__uint_as_float(pb));
        float gd = sqrtf(__uint_as_float(gb));
        bool tpos = gd < 0.2f;
        float z = (0.2f - pd) * 100.f;
        float p = 1.f / (1.f + expf(-z));
        p = fminf(fmaxf(p, 1e-6f), 1.f - 1e-6f);
        float l = tpos ? -logf(p) : -logf(1.f - p);
        if (tpos) { P = 1.f; Spos = l; } else { Sneg = l; }
        float over = fmaxf(pd - 0.1f, 0.f);
        float hub  = (over < 0.01f) ? (50.f * over * over) : (over - 0.005f);
        if (tpos) Shub = hub;
    }
    // warp reduce
#pragma unroll
    for (int off = 16; off; off >>= 1) {
        P    += __shfl_down_sync(0xFFFFFFFFu, P,    off);
        Spos += __shfl_down_sync(0xFFFFFFFFu, Spos, off);
        Sneg += __shfl_down_sync(0xFFFFFFFFu, Sneg, off);
        Shub += __shfl_down_sync(0xFFFFFFFFu, Shub, off);
    }
    __shared__ float s[4][8];
    int w = threadIdx.x >> 5, l = threadIdx.x & 31;
    if (l == 0) { s[0][w] = P; s[1][w] = Spos; s[2][w] = Sneg; s[3][w] = Shub; }
    __syncthreads();
    if (threadIdx.x == 0) {
        float a0 = 0, a1 = 0, a2 = 0, a3 = 0;
        int nw = (blockDim.x + 31) >> 5;
        for (int k = 0; k < nw; k++) { a0 += s[0][k]; a1 += s[1][k]; a2 += s[2][k]; a3 += s[3][k]; }
        atomicAdd(&g_acc[dir*4 + 0], (double)a0);
        atomicAdd(&g_acc[dir*4 + 1], (double)a1);
        atomicAdd(&g_acc[dir*4 + 2], (double)a2);
        atomicAdd(&g_acc[dir*4 + 3], (double)a3);
    }
}

__global__ void k_fin(float* out) {
    double Ph = g_acc[0], Sph = g_acc[1], Snh = g_acc[2], Shh = g_acc[3];
    double Po = g_acc[4], Spo = g_acc[5], Sno = g_acc[6], Sho = g_acc[7];
    double negh = (double)NH - Ph, nego = (double)NO - Po;
    double pwh = (negh + 1e-6) / (Ph + 1e-6);
    double pwo = (nego + 1e-6) / (Po + 1e-6);
    double bh = (pwh * Sph + Snh) / (double)NH;
    double bo = (pwo * Spo + Sno) / (double)NO;
    double Lbce = 0.5 * (bh + bo);
    double LhH = (Ph > 0.0) ? (Shh / fmax(Ph, 1.0)) : 0.0;
    double LhO = (Po > 0.0) ? (Sho / fmax(Po, 1.0)) : 0.0;
    out[0] = (float)(0.5 * Lbce + (LhH + LhO));
}

extern "C" void kernel_launch(void* const* d_in, const int* in_sizes, int n_in,
                              void* d_out, int out_size) {
    const float* h  = (const float*)d_in[0];
    const float* o  = (const float*)d_in[1];
    const float* gh = (const float*)d_in[2];
    const float* go = (const float*)d_in[3];

    k_init<<<(2*NH + 255)/256, 256>>>();
    k_prep<<<(2*NO + 255)/256, 256>>>(o, go);
    dim3 gp(RCHUNKS * JCHUNKS, BT, 2);      // 56 x 16 x 2 = 1792 blocks
    k_pair<<<gp, TPB>>>(h, gh);
    dim3 gl((NH + 255)/256, 2);
    k_loss<<<gl, 256>>>();
    k_fin<<<1, 1>>>((float*)d_out);
}

// round 2
// speedup vs baseline: 1.2632x; 1.2632x over previous
#include <cuda_runtime.h>
#include <math_constants.h>

#define BT 16
#define VH 6890
#define VO 2048
#define NH (BT*VH)          /* 110240 */
#define NO (BT*VO)          /* 32768  */
#define TPB 256
#define RPT 4
#define ROWCHUNK (TPB*RPT)  /* 1024 */
#define RCHUNKS ((VH+ROWCHUNK-1)/ROWCHUNK)  /* 7 */
#define JT 256
#define J2 (JT/2)           /* 128 packed pairs */
#define JCHUNKS (VO/JT)     /* 8 */

// Scratch (static __device__ — no allocations allowed)
__device__ float4   g_objP[2*NO];   // per object point: (-2x,-2y,-2z, x^2+y^2+z^2)
__device__ unsigned g_dh[2*NH];     // min d^2 bits, human rows  [ds][b][i]
__device__ unsigned g_do[2*NO];     // min d^2 bits, object cols [ds][b][j]
__device__ double   g_acc[8];       // [dir(h/o)][P, Spos, Sneg, Shub]

// ---- packed f32x2 helpers (Blackwell FFMA2 path) ----
union F2U { float2 f; unsigned long long u; };

__device__ __forceinline__ float2 fma2(float2 a, float2 b, float2 c) {
    F2U A, B, C, D; A.f = a; B.f = b; C.f = c;
    asm("fma.rn.f32x2 %0, %1, %2, %3;" : "=l"(D.u) : "l"(A.u), "l"(B.u), "l"(C.u));
    return D.f;
}
__device__ __forceinline__ float2 add2(float2 a, float2 b) {
    F2U A, B, D; A.f = a; B.f = b;
    asm("add.rn.f32x2 %0, %1, %2;" : "=l"(D.u) : "l"(A.u), "l"(B.u));
    return D.f;
}

// fused init + object preprocessing
__global__ void k_initprep(const float* __restrict__ o, const float* __restrict__ go) {
    int i = blockIdx.x * blockDim.x + threadIdx.x;
    if (i < 2*NH) g_dh[i] = 0x7F800000u;  // +inf
    if (i < 8)    g_acc[i] = 0.0;
    if (i < 2*NO) {
        g_do[i] = 0x7F800000u;
        int ds = i >> 15;            // NO == 1<<15
        int r  = i & (NO - 1);
        const float* p = (ds ? go : o) + r * 3;
        float x = p[0], y = p[1], z = p[2];
        g_objP[i] = make_float4(-2.f*x, -2.f*y, -2.f*z,
                                fmaf(x, x, fmaf(y, y, z*z)));
    }
}

__global__ void __launch_bounds__(TPB) k_pair(const float* __restrict__ h,
                                              const float* __restrict__ gh) {
    __shared__ float2   sOx[J2], sOy[J2], sOz[J2], sOw[J2];
    __shared__ unsigned sCol[JT];
    const int ds = blockIdx.z, b = blockIdx.y;
    const int rc = blockIdx.x / JCHUNKS, jc = blockIdx.x % JCHUNKS;
    const int t  = threadIdx.x;
    const int objOff = ds*NO + b*VO + jc*JT;

    // stage objects into packed SoA: half the threads pack two objects each
    if (t < J2) {
        float4 a = g_objP[objOff + 2*t];
        float4 c = g_objP[objOff + 2*t + 1];
        sOx[t] = make_float2(a.x, c.x);
        sOy[t] = make_float2(a.y, c.y);
        sOz[t] = make_float2(a.z, c.z);
        sOw[t] = make_float2(a.w, c.w);
    }
    sCol[t] = 0x7F800000u;

    const float* H = (ds ? gh : h) + (size_t)b * VH * 3;
    float2 hx2[RPT], hy2[RPT], hz2[RPT], hh2[RPT];
    float rmin[RPT];
    const int row0 = rc * ROWCHUNK + t;
#pragma unroll
    for (int k = 0; k < RPT; k++) {
        int row = row0 + k * TPB;
        float x = 0.f, y = 0.f, z = 0.f, s = CUDART_INF_F;
        if (row < VH) {
            x = H[row*3+0]; y = H[row*3+1]; z = H[row*3+2];
            s = fmaf(x, x, fmaf(y, y, z*z));
        }
        hx2[k] = make_float2(x, x);
        hy2[k] = make_float2(y, y);
        hz2[k] = make_float2(z, z);
        hh2[k] = make_float2(s, s);   // +inf for invalid rows -> never wins col-min
        rmin[k] = CUDART_INF_F;
    }
    __syncthreads();

#pragma unroll 2
    for (int j2 = 0; j2 < J2; j2++) {
        float2 ox2 = sOx[j2], oy2 = sOy[j2], oz2 = sOz[j2], ow2 = sOw[j2];
        float cmA = CUDART_INF_F, cmB = CUDART_INF_F;
#pragma unroll
        for (int k = 0; k < RPT; k++) {
            float2 q2 = fma2(hz2[k], oz2, ow2);   // oo - 2 h·o (two objects)
            q2 = fma2(hy2[k], oy2, q2);
            q2 = fma2(hx2[k], ox2, q2);
            rmin[k] = fminf(rmin[k], fminf(q2.x, q2.y));
            float2 c2 = add2(q2, hh2[k]);         // full d^2
            cmA = fminf(cmA, c2.x);
            cmB = fminf(cmB, c2.y);
        }
        unsigned uA = __float_as_uint(fmaxf(cmA, 0.f));  // >=0 -> uint order == float order
        unsigned uB = __float_as_uint(fmaxf(cmB, 0.f));
        uA = __reduce_min_sync(0xFFFFFFFFu, uA);
        uB = __reduce_min_sync(0xFFFFFFFFu, uB);
        if ((t & 31) == 0) {
            atomicMin(&sCol[2*j2],     uA);
            atomicMin(&sCol[2*j2 + 1], uB);
        }
    }
    __syncthreads();

    atomicMin(&g_do[objOff + t], sCol[t]);
#pragma unroll
    for (int k = 0; k < RPT; k++) {
        int row = row0 + k * TPB;
        if (row < VH) {
            float d2 = fmaxf(rmin[k] + hh2[k].x, 0.f);
            atomicMin(&g_dh[ds*NH + b*VH + row], __float_as_uint(d2));
        }
    }
}

__global__ void k_loss() {
    const int dir = blockIdx.y;          // 0 = human rows, 1 = object cols
    const int N   = dir ? NO : NH;
    float P = 0.f, Spos = 0.f, Sneg = 0.f, Shub = 0.f;
    for (int i = blockIdx.x * blockDim.x + threadIdx.x; i < N; i += gridDim.x * blockDim.x) {
        unsigned pb = dir ? g_do[i]      : g_dh[i];
        unsigned gb = dir ? g_do[NO + i] : g_dh[NH + i];
        float pd = sqrtf(__uint_as_float(pb));
        float gd = sqrtf(__uint_as_float(gb));
        bool tpos = gd < 0.2f;
        float z = (0.2f - pd) * 100.f;
        float p = 1.f / (1.f + expf(-z));
        p = fminf(fmaxf(p, 1e-6f), 1.f - 1e-6f);
        float l = tpos ? -logf(p) : -logf(1.f - p);
        if (tpos) { P += 1.f; Spos += l; } else { Sneg += l; }
        float over = fmaxf(pd - 0.1f, 0.f);
        float hub  = (over < 0.01f) ? (50.f * over * over) : (over - 0.005f);
        if (tpos) Shub += hub;
    }
    // warp reduce
#pragma unroll
    for (int off = 16; off; off >>= 1) {
        P    += __shfl_down_sync(0xFFFFFFFFu, P,    off);
        Spos += __shfl_down_sync(0xFFFFFFFFu, Spos, off);
        Sneg += __shfl_down_sync(0xFFFFFFFFu, Sneg, off);
        Shub += __shfl_down_sync(0xFFFFFFFFu, Shub, off);
    }
    __shared__ float s[4][8];
    int w = threadIdx.x >> 5, l = threadIdx.x & 31;
    if (l == 0) { s[0][w] = P; s[1][w] = Spos; s[2][w] = Sneg; s[3][w] = Shub; }
    __syncthreads();
    if (threadIdx.x == 0) {
        float a0 = 0, a1 = 0, a2 = 0, a3 = 0;
        int nw = (blockDim.x + 31) >> 5;
        for (int k = 0; k < nw; k++) { a0 += s[0][k]; a1 += s[1][k]; a2 += s[2][k]; a3 += s[3][k]; }
        atomicAdd(&g_acc[dir*4 + 0], (double)a0);
        atomicAdd(&g_acc[dir*4 + 1], (double)a1);
        atomicAdd(&g_acc[dir*4 + 2], (double)a2);
        atomicAdd(&g_acc[dir*4 + 3], (double)a3);
    }
}

__global__ void k_fin(float* out) {
    double Ph = g_acc[0], Sph = g_acc[1], Snh = g_acc[2], Shh = g_acc[3];
    double Po = g_acc[4], Spo = g_acc[5], Sno = g_acc[6], Sho = g_acc[7];
    double negh = (double)NH - Ph, nego = (double)NO - Po;
    double pwh = (negh + 1e-6) / (Ph + 1e-6);
    double pwo = (nego + 1e-6) / (Po + 1e-6);
    double bh = (pwh * Sph + Snh) / (double)NH;
    double bo = (pwo * Spo + Sno) / (double)NO;
    double Lbce = 0.5 * (bh + bo);
    double LhH = (Ph > 0.0) ? (Shh / fmax(Ph, 1.0)) : 0.0;
    double LhO = (Po > 0.0) ? (Sho / fmax(Po, 1.0)) : 0.0;
    out[0] = (float)(0.5 * Lbce + (LhH + LhO));
}

extern "C" void kernel_launch(void* const* d_in, const int* in_sizes, int n_in,
                              void* d_out, int out_size) {
    const float* h  = (const float*)d_in[0];
    const float* o  = (const float*)d_in[1];
    const float* gh = (const float*)d_in[2];
    const float* go = (const float*)d_in[3];

    k_initprep<<<(2*NH + 255)/256, 256>>>(o, go);
    dim3 gp(RCHUNKS * JCHUNKS, BT, 2);      // 56 x 16 x 2 = 1792 blocks
    k_pair<<<gp, TPB>>>(h, gh);
    dim3 gl(64, 2);
    k_loss<<<gl, 256>>>();
    k_fin<<<1, 1>>>((float*)d_out);
}